// round 1
// baseline (speedup 1.0000x reference)
#include <cuda_runtime.h>
#include <cstdint>

// Problem constants (fixed by the reference)
#define HW_TOTAL (512 * 512)          // 262144 pixels per batch image
#define BATCH 32
#define PSAMP 8192
#define NSAMP (BATCH * PSAMP)         // 262144 samples per sample tensor
#define CHUNK 2048                    // elements per count/scatter block
#define CHUNKS_PER_BATCH (HW_TOTAL / CHUNK)   // 128
#define NCHUNKS (BATCH * CHUNKS_PER_BATCH)    // 4096
#define EPS_F 1e-5f

// -------- device scratch (static globals: no runtime allocation) --------
__device__ int    g_chunkCnt[NCHUNKS];
__device__ int    g_chunkOff[NCHUNKS];
__device__ int    g_validNum[BATCH];
__device__ int    g_posmap[(size_t)BATCH * HW_TOTAL];   // rank -> in-batch flat index
__device__ double g_sum1, g_sum2;
__device__ int    g_cnt1, g_cnt2;

// -------- kernel 0: zero accumulators --------
__global__ void k_init() {
    g_sum1 = 0.0; g_sum2 = 0.0; g_cnt1 = 0; g_cnt2 = 0;
}

// -------- kernel 1: per-chunk valid counts --------
__global__ void __launch_bounds__(256) k_count(const int* __restrict__ mask) {
    int chunk = blockIdx.x;
    int t = threadIdx.x;
    const int4* p = reinterpret_cast<const int4*>(mask + (size_t)chunk * CHUNK);
    int4 a = p[t * 2];
    int4 b = p[t * 2 + 1];
    int c = (a.x != 0) + (a.y != 0) + (a.z != 0) + (a.w != 0)
          + (b.x != 0) + (b.y != 0) + (b.z != 0) + (b.w != 0);

    #pragma unroll
    for (int o = 16; o; o >>= 1) c += __shfl_down_sync(0xFFFFFFFFu, c, o);

    __shared__ int ws[8];
    int lane = t & 31, wid = t >> 5;
    if (lane == 0) ws[wid] = c;
    __syncthreads();
    if (wid == 0) {
        int v = (lane < 8) ? ws[lane] : 0;
        #pragma unroll
        for (int o = 4; o; o >>= 1) v += __shfl_down_sync(0xFFFFFFFFu, v, o);
        if (lane == 0) g_chunkCnt[chunk] = v;
    }
}

// -------- kernel 2: per-batch exclusive scan of chunk counts --------
// One block of 1024 threads; warp w owns batch w (128 chunks, 4 per lane).
__global__ void __launch_bounds__(1024) k_scan() {
    int t = threadIdx.x;
    int b = t >> 5, lane = t & 31;
    int base = b * CHUNKS_PER_BATCH + lane * 4;
    int c0 = g_chunkCnt[base + 0];
    int c1 = g_chunkCnt[base + 1];
    int c2 = g_chunkCnt[base + 2];
    int c3 = g_chunkCnt[base + 3];
    int s = c0 + c1 + c2 + c3;
    int inc = s;
    #pragma unroll
    for (int o = 1; o < 32; o <<= 1) {
        int v = __shfl_up_sync(0xFFFFFFFFu, inc, o);
        if (lane >= o) inc += v;
    }
    int exc = inc - s;
    g_chunkOff[base + 0] = exc;
    g_chunkOff[base + 1] = exc + c0;
    g_chunkOff[base + 2] = exc + c0 + c1;
    g_chunkOff[base + 3] = exc + c0 + c1 + c2;
    int tot = __shfl_sync(0xFFFFFFFFu, inc, 31);
    if (lane == 0) g_validNum[b] = tot;
}

// -------- kernel 3: scatter rank -> in-batch position --------
__global__ void __launch_bounds__(256) k_scatter(const int* __restrict__ mask) {
    int chunk = blockIdx.x;
    int b   = chunk / CHUNKS_PER_BATCH;
    int cib = chunk % CHUNKS_PER_BATCH;
    int t = threadIdx.x, lane = t & 31, wid = t >> 5;

    const int4* p = reinterpret_cast<const int4*>(mask + (size_t)chunk * CHUNK);
    int4 a = p[t * 2];
    int4 q = p[t * 2 + 1];
    int m[8];
    m[0] = (a.x != 0); m[1] = (a.y != 0); m[2] = (a.z != 0); m[3] = (a.w != 0);
    m[4] = (q.x != 0); m[5] = (q.y != 0); m[6] = (q.z != 0); m[7] = (q.w != 0);
    int c = m[0] + m[1] + m[2] + m[3] + m[4] + m[5] + m[6] + m[7];

    // warp inclusive scan of per-thread counts
    int inc = c;
    #pragma unroll
    for (int o = 1; o < 32; o <<= 1) {
        int v = __shfl_up_sync(0xFFFFFFFFu, inc, o);
        if (lane >= o) inc += v;
    }

    __shared__ int wsum[8];
    __shared__ int wexc[8];
    if (lane == 31) wsum[wid] = inc;
    __syncthreads();
    if (wid == 0 && lane < 8) {
        int v = wsum[lane];
        int i8 = v;
        #pragma unroll
        for (int o = 1; o < 8; o <<= 1) {
            int u = __shfl_up_sync(0xFFu, i8, o);
            if (lane >= o) i8 += u;
        }
        wexc[lane] = i8 - v;
    }
    __syncthreads();

    int rank = g_chunkOff[chunk] + wexc[wid] + (inc - c);
    int idxbase = cib * CHUNK + t * 8;
    int* pm = g_posmap + (size_t)b * HW_TOTAL;
    #pragma unroll
    for (int k = 0; k < 8; k++) {
        if (m[k]) { pm[rank] = idxbase + k; rank++; }
    }
}

// -------- kernel 4: sample gather + reduction --------
__global__ void __launch_bounds__(256) k_sample(const float* __restrict__ d3,
                                                const float* __restrict__ dp,
                                                const int* __restrict__ s1,
                                                const int* __restrict__ s2) {
    int lane = threadIdx.x & 31, wid = threadIdx.x >> 5;
    float ls1 = 0.f, ls2 = 0.f;
    int lc1 = 0, lc2 = 0;

    for (int i = blockIdx.x * blockDim.x + threadIdx.x; i < NSAMP;
         i += gridDim.x * blockDim.x) {
        int b = i >> 13;                        // PSAMP = 8192
        int vn = g_validNum[b];
        size_t bo = (size_t)b * HW_TOTAL;
        int j1 = s1[i] % vn;
        int j2 = s2[i] % vn;
        int p1 = g_posmap[bo + j1];
        int p2 = g_posmap[bo + j2];
        float av = d3[bo + p1];
        float bv = d3[bo + p2];
        float diff = dp[bo + p1] - dp[bo + p2];
        if (av > bv + EPS_F) { ls1 += fmaxf(-diff, 0.f); lc1++; }
        if (av < bv - EPS_F) { ls2 += fmaxf(diff, 0.f);  lc2++; }
    }

    #pragma unroll
    for (int o = 16; o; o >>= 1) {
        ls1 += __shfl_down_sync(0xFFFFFFFFu, ls1, o);
        ls2 += __shfl_down_sync(0xFFFFFFFFu, ls2, o);
        lc1 += __shfl_down_sync(0xFFFFFFFFu, lc1, o);
        lc2 += __shfl_down_sync(0xFFFFFFFFu, lc2, o);
    }
    __shared__ float sf1[8], sf2[8];
    __shared__ int   si1[8], si2[8];
    if (lane == 0) { sf1[wid] = ls1; sf2[wid] = ls2; si1[wid] = lc1; si2[wid] = lc2; }
    __syncthreads();
    if (wid == 0) {
        float v1 = (lane < 8) ? sf1[lane] : 0.f;
        float v2 = (lane < 8) ? sf2[lane] : 0.f;
        int   i1 = (lane < 8) ? si1[lane] : 0;
        int   i2 = (lane < 8) ? si2[lane] : 0;
        #pragma unroll
        for (int o = 4; o; o >>= 1) {
            v1 += __shfl_down_sync(0xFFFFFFFFu, v1, o);
            v2 += __shfl_down_sync(0xFFFFFFFFu, v2, o);
            i1 += __shfl_down_sync(0xFFFFFFFFu, i1, o);
            i2 += __shfl_down_sync(0xFFFFFFFFu, i2, o);
        }
        if (lane == 0) {
            atomicAdd(&g_sum1, (double)v1);
            atomicAdd(&g_sum2, (double)v2);
            atomicAdd(&g_cnt1, i1);
            atomicAdd(&g_cnt2, i2);
        }
    }
}

// -------- kernel 5: finalize --------
__global__ void k_final(float* __restrict__ out) {
    float l1 = (float)(g_sum1 / (double)g_cnt1);
    float l2 = (float)(g_sum2 / (double)g_cnt2);
    out[0] = 0.5f * (l1 + l2);
}

extern "C" void kernel_launch(void* const* d_in, const int* in_sizes, int n_in,
                              void* d_out, int out_size) {
    const float* d3   = (const float*)d_in[0];   // depth_3dmm
    const float* dp   = (const float*)d_in[1];   // depth_pigan
    const int*   mask = (const int*)d_in[2];
    const int*   s1   = (const int*)d_in[3];
    const int*   s2   = (const int*)d_in[4];

    k_init<<<1, 1>>>();
    k_count<<<NCHUNKS, 256>>>(mask);
    k_scan<<<1, 1024>>>();
    k_scatter<<<NCHUNKS, 256>>>(mask);
    k_sample<<<256, 256>>>(d3, dp, s1, s2);
    k_final<<<1, 1>>>((float*)d_out);
}

// round 3
// speedup vs baseline: 1.2920x; 1.2920x over previous
#include <cuda_runtime.h>
#include <cstdint>

// Problem constants (fixed by the reference)
#define HW_TOTAL (512 * 512)                  // 262144 pixels per batch image
#define BATCH 32
#define PSAMP 8192
#define NSAMP (BATCH * PSAMP)                 // 262144 samples
#define CHUNK 2048                            // elements per chunk/block
#define CHUNKS_PER_BATCH (HW_TOTAL / CHUNK)   // 128
#define NCHUNKS (BATCH * CHUNKS_PER_BATCH)    // 4096
#define EPS_F 1e-5f

// -------- device scratch (static globals: no runtime allocation) --------
__device__ unsigned char g_bitmask[(size_t)BATCH * HW_TOTAL / 8];  // 1 MB packed mask
__device__ int    g_chunkCnt[NCHUNKS];
__device__ int    g_chunkOff[NCHUNKS];
__device__ int    g_validNum[BATCH];
__device__ int    g_posmap[(size_t)BATCH * HW_TOTAL];  // rank -> in-batch flat index
__device__ double g_sum1, g_sum2;
__device__ int    g_cnt1, g_cnt2;

// -------- kernel 1: count valid per chunk + emit packed bitmask --------
__global__ void __launch_bounds__(256) k_count(const int* __restrict__ mask) {
    int chunk = blockIdx.x;
    int t = threadIdx.x;
    const int4* p = reinterpret_cast<const int4*>(mask + (size_t)chunk * CHUNK);
    int4 a = p[t * 2];
    int4 b = p[t * 2 + 1];

    int byte = (a.x != 0)      | (a.y != 0) << 1 | (a.z != 0) << 2 | (a.w != 0) << 3
             | (b.x != 0) << 4 | (b.y != 0) << 5 | (b.z != 0) << 6 | (b.w != 0) << 7;
    g_bitmask[(size_t)chunk * 256 + t] = (unsigned char)byte;

    int c = __popc(byte);
    #pragma unroll
    for (int o = 16; o; o >>= 1) c += __shfl_down_sync(0xFFFFFFFFu, c, o);

    __shared__ int ws[8];
    int lane = t & 31, wid = t >> 5;
    if (lane == 0) ws[wid] = c;
    __syncthreads();
    if (wid == 0) {
        int v = (lane < 8) ? ws[lane] : 0;
        #pragma unroll
        for (int o = 4; o; o >>= 1) v += __shfl_down_sync(0xFFFFFFFFu, v, o);
        if (lane == 0) g_chunkCnt[chunk] = v;
    }
}

// -------- kernel 2: per-batch exclusive scan of chunk counts (+ zero accums)
// One block of 1024 threads; warp w owns batch w (128 chunks, 4 per lane).
__global__ void __launch_bounds__(1024) k_scan() {
    int t = threadIdx.x;
    if (t == 0) { g_sum1 = 0.0; g_sum2 = 0.0; g_cnt1 = 0; g_cnt2 = 0; }
    int b = t >> 5, lane = t & 31;
    int base = b * CHUNKS_PER_BATCH + lane * 4;
    int c0 = g_chunkCnt[base + 0];
    int c1 = g_chunkCnt[base + 1];
    int c2 = g_chunkCnt[base + 2];
    int c3 = g_chunkCnt[base + 3];
    int s = c0 + c1 + c2 + c3;
    int inc = s;
    #pragma unroll
    for (int o = 1; o < 32; o <<= 1) {
        int v = __shfl_up_sync(0xFFFFFFFFu, inc, o);
        if (lane >= o) inc += v;
    }
    int exc = inc - s;
    g_chunkOff[base + 0] = exc;
    g_chunkOff[base + 1] = exc + c0;
    g_chunkOff[base + 2] = exc + c0 + c1;
    g_chunkOff[base + 3] = exc + c0 + c1 + c2;
    int tot = __shfl_sync(0xFFFFFFFFu, inc, 31);
    if (lane == 0) g_validNum[b] = tot;
}

// -------- kernel 3: scatter from bitmask, staged in smem, coalesced flush ---
__global__ void __launch_bounds__(256) k_scatter() {
    const int chunk = blockIdx.x;
    const int b   = chunk >> 7;            // CHUNKS_PER_BATCH = 128
    const int cib = chunk & 127;
    const int t = threadIdx.x, lane = t & 31, wid = t >> 5;

    const unsigned byte = g_bitmask[(size_t)chunk * 256 + t];
    const int c = __popc(byte);

    // warp inclusive scan of per-thread counts
    int inc = c;
    #pragma unroll
    for (int o = 1; o < 32; o <<= 1) {
        int v = __shfl_up_sync(0xFFFFFFFFu, inc, o);
        if (lane >= o) inc += v;
    }

    __shared__ int wsum[8];
    __shared__ int wexc[8];
    __shared__ int sidx[CHUNK];            // 8 KB staging
    if (lane == 31) wsum[wid] = inc;
    __syncthreads();
    if (wid == 0 && lane < 8) {
        int v = wsum[lane];
        int i8 = v;
        #pragma unroll
        for (int o = 1; o < 8; o <<= 1) {
            int u = __shfl_up_sync(0xFFu, i8, o);
            if (lane >= o) i8 += u;
        }
        wexc[lane] = i8 - v;
    }
    __syncthreads();

    // stage local compaction (smem scatter: bank-granular, cheap)
    int lr = wexc[wid] + (inc - c);
    const int idxbase = cib * CHUNK + t * 8;
    #pragma unroll
    for (int k = 0; k < 8; k++) {
        if ((byte >> k) & 1) { sidx[lr] = idxbase + k; lr++; }
    }
    __syncthreads();

    // coalesced flush to global posmap
    const int total = g_chunkCnt[chunk];
    const int base  = g_chunkOff[chunk];
    int* pm = g_posmap + (size_t)b * HW_TOTAL + base;
    for (int i = t; i < total; i += 256) pm[i] = sidx[i];
}

// -------- kernel 4: sample gather + reduction --------
__global__ void __launch_bounds__(256) k_sample(const float* __restrict__ d3,
                                                const float* __restrict__ dp,
                                                const int* __restrict__ s1,
                                                const int* __restrict__ s2) {
    int lane = threadIdx.x & 31, wid = threadIdx.x >> 5;
    float ls1 = 0.f, ls2 = 0.f;
    int lc1 = 0, lc2 = 0;

    for (int i = blockIdx.x * blockDim.x + threadIdx.x; i < NSAMP;
         i += gridDim.x * blockDim.x) {
        int b = i >> 13;                        // PSAMP = 8192
        int vn = g_validNum[b];
        size_t bo = (size_t)b * HW_TOTAL;
        int j1 = s1[i] % vn;
        int j2 = s2[i] % vn;
        int p1 = g_posmap[bo + j1];
        int p2 = g_posmap[bo + j2];
        float av = d3[bo + p1];
        float bv = d3[bo + p2];
        float diff = dp[bo + p1] - dp[bo + p2];
        if (av > bv + EPS_F) { ls1 += fmaxf(-diff, 0.f); lc1++; }
        if (av < bv - EPS_F) { ls2 += fmaxf(diff, 0.f);  lc2++; }
    }

    #pragma unroll
    for (int o = 16; o; o >>= 1) {
        ls1 += __shfl_down_sync(0xFFFFFFFFu, ls1, o);
        ls2 += __shfl_down_sync(0xFFFFFFFFu, ls2, o);
        lc1 += __shfl_down_sync(0xFFFFFFFFu, lc1, o);
        lc2 += __shfl_down_sync(0xFFFFFFFFu, lc2, o);
    }
    __shared__ float sf1[8], sf2[8];
    __shared__ int   si1[8], si2[8];
    if (lane == 0) { sf1[wid] = ls1; sf2[wid] = ls2; si1[wid] = lc1; si2[wid] = lc2; }
    __syncthreads();
    if (wid == 0) {
        float v1 = (lane < 8) ? sf1[lane] : 0.f;
        float v2 = (lane < 8) ? sf2[lane] : 0.f;
        int   i1 = (lane < 8) ? si1[lane] : 0;
        int   i2 = (lane < 8) ? si2[lane] : 0;
        #pragma unroll
        for (int o = 4; o; o >>= 1) {
            v1 += __shfl_down_sync(0xFFFFFFFFu, v1, o);
            v2 += __shfl_down_sync(0xFFFFFFFFu, v2, o);
            i1 += __shfl_down_sync(0xFFFFFFFFu, i1, o);
            i2 += __shfl_down_sync(0xFFFFFFFFu, i2, o);
        }
        if (lane == 0) {
            atomicAdd(&g_sum1, (double)v1);
            atomicAdd(&g_sum2, (double)v2);
            atomicAdd(&g_cnt1, i1);
            atomicAdd(&g_cnt2, i2);
        }
    }
}

// -------- kernel 5: finalize --------
__global__ void k_final(float* __restrict__ out) {
    float l1 = (float)(g_sum1 / (double)g_cnt1);
    float l2 = (float)(g_sum2 / (double)g_cnt2);
    out[0] = 0.5f * (l1 + l2);
}

extern "C" void kernel_launch(void* const* d_in, const int* in_sizes, int n_in,
                              void* d_out, int out_size) {
    const float* d3   = (const float*)d_in[0];   // depth_3dmm
    const float* dp   = (const float*)d_in[1];   // depth_pigan
    const int*   mask = (const int*)d_in[2];
    const int*   s1   = (const int*)d_in[3];
    const int*   s2   = (const int*)d_in[4];

    k_count<<<NCHUNKS, 256>>>(mask);
    k_scan<<<1, 1024>>>();
    k_scatter<<<NCHUNKS, 256>>>();
    k_sample<<<1024, 256>>>(d3, dp, s1, s2);
    k_final<<<1, 1>>>((float*)d_out);
}

// round 4
// speedup vs baseline: 1.4994x; 1.1605x over previous
#include <cuda_runtime.h>
#include <cstdint>

// Problem constants (fixed by the reference)
#define HW_TOTAL (512 * 512)                  // 262144 pixels per batch image
#define BATCH 32
#define PSAMP 8192
#define NSAMP (BATCH * PSAMP)                 // 262144 samples
#define CHUNK 2048                            // pixels per chunk (one block)
#define CPB 128                               // chunks per batch
#define NCHUNKS (BATCH * CPB)                 // 4096
#define EPS_F 1e-5f

// -------- device scratch (static globals: no runtime allocation) --------
__device__ __align__(256) unsigned char g_bytes[(size_t)NCHUNKS * 256]; // 1 MB packed mask
__device__ __align__(16)  unsigned short g_subOff[NCHUNKS * 8];         // 64 KB: per-chunk 256-px group offsets
__device__ int      g_chunkCnt[NCHUNKS];
__device__ int      g_chunkOff[NCHUNKS];      // exclusive offsets within batch
__device__ int      g_validNum[BATCH];
__device__ double   g_sum1, g_sum2;
__device__ int      g_cnt1, g_cnt2;
__device__ unsigned g_done1, g_done2;         // zero-initialized; self-resetting

// ======== kernel 1: mask -> bitmask + subOff + chunk counts; last block scans
__global__ void __launch_bounds__(256) k_count(const int* __restrict__ mask) {
    const int chunk = blockIdx.x;
    const int t = threadIdx.x, lane = t & 31, wid = t >> 5;

    // ---- read 8 mask ints, build 8-bit mask byte (bit k = pixel t*8+k) ----
    const int4* p = reinterpret_cast<const int4*>(mask + (size_t)chunk * CHUNK);
    int4 a = p[t * 2];
    int4 b = p[t * 2 + 1];
    unsigned byte = (unsigned)(a.x != 0)      | (unsigned)(a.y != 0) << 1
                  | (unsigned)(a.z != 0) << 2 | (unsigned)(a.w != 0) << 3
                  | (unsigned)(b.x != 0) << 4 | (unsigned)(b.y != 0) << 5
                  | (unsigned)(b.z != 0) << 6 | (unsigned)(b.w != 0) << 7;
    g_bytes[(size_t)chunk * 256 + t] = (unsigned char)byte;

    // ---- warp (=256-px group) popcount sums ----
    int c = __popc(byte);
    #pragma unroll
    for (int o = 16; o; o >>= 1) c += __shfl_down_sync(0xFFFFFFFFu, c, o);

    __shared__ int ws[8];
    if (lane == 0) ws[wid] = c;
    __syncthreads();

    if (t == 0) {
        // exclusive scan of 8 group sums -> subOff (u16 x8 = one 16B store)
        __align__(16) unsigned short so[8];
        int e = 0;
        #pragma unroll
        for (int g = 0; g < 8; g++) { so[g] = (unsigned short)e; e += ws[g]; }
        *reinterpret_cast<uint4*>(&g_subOff[chunk * 8]) =
            *reinterpret_cast<const uint4*>(so);
        g_chunkCnt[chunk] = e;
    }

    // ---- last-block-done: per-batch scan of chunk counts + zero accumulators
    __shared__ int isLast;
    __threadfence();
    if (t == 0) isLast = (atomicAdd(&g_done1, 1) == NCHUNKS - 1);
    __syncthreads();
    if (!isLast) return;

    if (t == 0) {
        g_done1 = 0;                          // reset for next graph replay
        g_sum1 = 0.0; g_sum2 = 0.0; g_cnt1 = 0; g_cnt2 = 0;
    }
    // 8 warps; warp w scans batches w, w+8, w+16, w+24 (128 counts, 4/lane)
    for (int bb = wid; bb < BATCH; bb += 8) {
        int base = bb * CPB + lane * 4;
        int c0 = __ldcg(&g_chunkCnt[base + 0]);
        int c1 = __ldcg(&g_chunkCnt[base + 1]);
        int c2 = __ldcg(&g_chunkCnt[base + 2]);
        int c3 = __ldcg(&g_chunkCnt[base + 3]);
        int s4 = c0 + c1 + c2 + c3;
        int inc = s4;
        #pragma unroll
        for (int o = 1; o < 32; o <<= 1) {
            int v = __shfl_up_sync(0xFFFFFFFFu, inc, o);
            if (lane >= o) inc += v;
        }
        int exc = inc - s4;
        g_chunkOff[base + 0] = exc;
        g_chunkOff[base + 1] = exc + c0;
        g_chunkOff[base + 2] = exc + c0 + c1;
        g_chunkOff[base + 3] = exc + c0 + c1 + c2;
        int tot = __shfl_sync(0xFFFFFFFFu, inc, 31);
        if (lane == 0) g_validNum[bb] = tot;
    }
}

// ======== rank -> original pixel position (select) ========
// scoff: smem chunk offsets (128, exclusive, scoff[0]==0) for this batch.
__device__ __forceinline__ int rank_select(int j, int batchChunkBase,
                                           const int* scoff) {
    // 1) largest c with scoff[c] <= j  (7-step binary search in smem)
    int c = 0;
    #pragma unroll
    for (int st = 64; st; st >>= 1)
        if (c + st < CPB && scoff[c + st] <= j) c += st;
    int r = j - scoff[c];
    const int chunk = batchChunkBase + c;

    // 2) 8 sub-group offsets (u16, nondecreasing, sub[0]==0) in one 16B load
    uint4 q = *reinterpret_cast<const uint4*>(&g_subOff[chunk * 8]);
    int x1 = (int)(q.x >> 16);          // sub[1]
    int x2 = (int)(q.y & 0xFFFF);       // sub[2]
    int x3 = (int)(q.y >> 16);          // sub[3]
    int x4 = (int)(q.z & 0xFFFF);       // sub[4]
    int x5 = (int)(q.z >> 16);          // sub[5]
    int x6 = (int)(q.w & 0xFFFF);       // sub[6]
    int x7 = (int)(q.w >> 16);          // sub[7]
    int s   = (x1 <= r) + (x2 <= r) + (x3 <= r) + (x4 <= r)
            + (x5 <= r) + (x6 <= r) + (x7 <= r);
    int off = 0;
    off = (x1 <= r) ? x1 : off;  off = (x2 <= r) ? x2 : off;
    off = (x3 <= r) ? x3 : off;  off = (x4 <= r) ? x4 : off;
    off = (x5 <= r) ? x5 : off;  off = (x6 <= r) ? x6 : off;
    off = (x7 <= r) ? x7 : off;
    int r2 = r - off;

    // 3) walk 4 bit-words of the 256-px sub-group (one 32B sector)
    const ulonglong2* bp = reinterpret_cast<const ulonglong2*>(
        g_bytes + (size_t)chunk * 256 + s * 32);
    ulonglong2 q0 = bp[0];
    ulonglong2 q1 = bp[1];
    unsigned long long w = q0.x;
    int wsel = 0;
    int p0 = __popcll(q0.x);
    if (r2 >= p0) {
        r2 -= p0;
        int p1 = __popcll(q0.y);
        if (r2 >= p1) {
            r2 -= p1;
            int p2 = __popcll(q1.x);
            if (r2 >= p2) { r2 -= p2; w = q1.y; wsel = 3; }
            else          {           w = q1.x; wsel = 2; }
        } else            {           w = q0.y; wsel = 1; }
    }
    unsigned lo = (unsigned)w;
    int pl = __popc(lo);
    int bit = (r2 < pl) ? (int)__fns(lo, 0, r2 + 1)
                        : 32 + (int)__fns((unsigned)(w >> 32), 0, r2 - pl + 1);
    return c * CHUNK + s * 256 + wsel * 64 + bit;
}

// ======== kernel 2: sample gather + reduction; last block finalizes ========
__global__ void __launch_bounds__(256) k_sample(const float* __restrict__ d3,
                                                const float* __restrict__ dp,
                                                const int* __restrict__ s1,
                                                const int* __restrict__ s2,
                                                float* __restrict__ out) {
    const int i = blockIdx.x * 256 + threadIdx.x;    // grid covers NSAMP exactly
    const int lane = threadIdx.x & 31, wid = threadIdx.x >> 5;
    const int b = i >> 13;                           // 8192 samples/batch; 32 blocks/batch

    __shared__ int scoff[CPB];
    __shared__ int svn;
    if (threadIdx.x < CPB) scoff[threadIdx.x] = g_chunkOff[b * CPB + threadIdx.x];
    if (threadIdx.x == 0)  svn = g_validNum[b];
    __syncthreads();

    const int vn = svn;
    const int bcb = b * CPB;
    const size_t bo = (size_t)b * HW_TOTAL;

    const int j1 = s1[i] % vn;
    const int j2 = s2[i] % vn;
    const int p1 = rank_select(j1, bcb, scoff);
    const int p2 = rank_select(j2, bcb, scoff);

    const float av = d3[bo + p1];
    const float bv = d3[bo + p2];
    const float diff = dp[bo + p1] - dp[bo + p2];

    float ls1 = 0.f, ls2 = 0.f;
    int lc1 = 0, lc2 = 0;
    if (av > bv + EPS_F) { ls1 = fmaxf(-diff, 0.f); lc1 = 1; }
    if (av < bv - EPS_F) { ls2 = fmaxf(diff, 0.f);  lc2 = 1; }

    #pragma unroll
    for (int o = 16; o; o >>= 1) {
        ls1 += __shfl_down_sync(0xFFFFFFFFu, ls1, o);
        ls2 += __shfl_down_sync(0xFFFFFFFFu, ls2, o);
        lc1 += __shfl_down_sync(0xFFFFFFFFu, lc1, o);
        lc2 += __shfl_down_sync(0xFFFFFFFFu, lc2, o);
    }
    __shared__ float sf1[8], sf2[8];
    __shared__ int   si1[8], si2[8];
    if (lane == 0) { sf1[wid] = ls1; sf2[wid] = ls2; si1[wid] = lc1; si2[wid] = lc2; }
    __syncthreads();
    if (wid == 0) {
        float v1 = (lane < 8) ? sf1[lane] : 0.f;
        float v2 = (lane < 8) ? sf2[lane] : 0.f;
        int   i1 = (lane < 8) ? si1[lane] : 0;
        int   i2 = (lane < 8) ? si2[lane] : 0;
        #pragma unroll
        for (int o = 4; o; o >>= 1) {
            v1 += __shfl_down_sync(0xFFFFFFFFu, v1, o);
            v2 += __shfl_down_sync(0xFFFFFFFFu, v2, o);
            i1 += __shfl_down_sync(0xFFFFFFFFu, i1, o);
            i2 += __shfl_down_sync(0xFFFFFFFFu, i2, o);
        }
        if (lane == 0) {
            atomicAdd(&g_sum1, (double)v1);
            atomicAdd(&g_sum2, (double)v2);
            atomicAdd(&g_cnt1, i1);
            atomicAdd(&g_cnt2, i2);
        }
    }

    // ---- last-block finalize ----
    __shared__ int isLast;
    __threadfence();
    __syncthreads();
    if (threadIdx.x == 0) {
        isLast = (atomicAdd(&g_done2, 1) == gridDim.x - 1);
        if (isLast) {
            g_done2 = 0;                       // reset for next graph replay
            double a1 = *(volatile double*)&g_sum1;
            double a2 = *(volatile double*)&g_sum2;
            int    n1 = *(volatile int*)&g_cnt1;
            int    n2 = *(volatile int*)&g_cnt2;
            float l1 = (float)(a1 / (double)n1);
            float l2 = (float)(a2 / (double)n2);
            out[0] = 0.5f * (l1 + l2);
        }
    }
}

extern "C" void kernel_launch(void* const* d_in, const int* in_sizes, int n_in,
                              void* d_out, int out_size) {
    const float* d3   = (const float*)d_in[0];   // depth_3dmm
    const float* dp   = (const float*)d_in[1];   // depth_pigan
    const int*   mask = (const int*)d_in[2];
    const int*   s1   = (const int*)d_in[3];
    const int*   s2   = (const int*)d_in[4];

    k_count<<<NCHUNKS, 256>>>(mask);
    k_sample<<<NSAMP / 256, 256>>>(d3, dp, s1, s2, (float*)d_out);
}